// round 5
// baseline (speedup 1.0000x reference)
#include <cuda_runtime.h>
#include <cuda_bf16.h>
#include <cooperative_groups.h>
#include <cstdint>

namespace cg = cooperative_groups;

#define BB 32
#define TT 2048
#define DD 256
#define HH 256
#define G4 1024
#define KK 8

// ---------------- scratch (device globals; no runtime allocation) ----------------
__device__ float g_G[(size_t)2 * BB * TT * G4];    // gate pre-activations, both dirs
__device__ float g_h[(size_t)2 * BB * TT * HH];    // h_f / h_b (backward already un-reversed)
__device__ float g_emis[(size_t)BB * TT * KK];
__device__ float g_res[BB];

__device__ __forceinline__ uint32_t cvta_s(const void* p) {
    return (uint32_t)__cvta_generic_to_shared(p);
}

// packed f32x2 helpers (Blackwell FFMA2 path — only via PTX fma.rn.f32x2)
#define FMA2(acc, a, b) asm("fma.rn.f32x2 %0, %1, %2, %0;" : "+l"(acc) : "l"(a), "l"(b))
#define ADD2(d, a, b)   asm("add.rn.f32x2 %0, %1, %2;" : "=l"(d) : "l"(a), "l"(b))
#define PACK2(d, s)     asm("mov.b64 %0, {%1, %1};" : "=l"(d) : "f"(s))
#define UNPACK2(lo, hi, v) asm("mov.b64 {%0, %1}, %2;" : "=f"(lo), "=f"(hi) : "l"(v))
#define LDS_V2U64(a, b, addr) \
    asm("ld.shared.v2.b64 {%0, %1}, [%2];" : "=l"(a), "=l"(b) : "r"(addr))
#define LDS_V4F32(w0, w1, w2, w3, addr) \
    asm("ld.shared.v4.f32 {%0, %1, %2, %3}, [%4];" \
        : "=f"(w0), "=f"(w1), "=f"(w2), "=f"(w3) : "r"(addr))

__device__ __forceinline__ float sigf(float x)   { return 1.0f / (1.0f + __expf(-x)); }
__device__ __forceinline__ float tanhf2(float x) { return 2.0f / (1.0f + __expf(-2.0f * x)) - 1.0f; }

// ---------------- Kernel 1: input projection GEMM (f32x2) ----------------
__global__ void __launch_bounds__(256, 3) proj_kernel(
    const float* __restrict__ x,
    const float* __restrict__ wf, const float* __restrict__ bif, const float* __restrict__ bhf,
    const float* __restrict__ wb, const float* __restrict__ bib, const float* __restrict__ bhb)
{
    __shared__ float sA[32 * 132];
    __shared__ float sB[32 * 68];

    const int dir = blockIdx.z;
    const float* w  = dir ? wb  : wf;
    const float* bi = dir ? bib : bif;
    const float* bh = dir ? bhb : bhf;

    const int tid = threadIdx.x;
    const int bM = blockIdx.x * 128;
    const int bN = blockIdx.y * 64;
    const int ty = tid >> 4;
    const int tx = tid & 15;

    unsigned long long acc[8][2];
#pragma unroll
    for (int i = 0; i < 8; ++i) { acc[i][0] = 0ull; acc[i][1] = 0ull; }

    const int rowL = tid >> 3;
    const int kL   = (tid & 7) << 2;
    const float* xg = x + (size_t)(bM + rowL) * DD + kL;
    const float* wg = w + (size_t)(bN + rowL) * DD + kL;

    const uint32_t sAa = cvta_s(sA) + ty * 32;
    const uint32_t sBa = cvta_s(sB) + tx * 16;

    for (int kt = 0; kt < 8; ++kt) {
        const int k0 = kt * 32;
#pragma unroll
        for (int p = 0; p < 4; ++p) {
            float4 v = *(const float4*)(xg + (size_t)p * 32 * DD + k0);
            int m = rowL + p * 32;
            sA[(kL + 0) * 132 + m] = v.x;
            sA[(kL + 1) * 132 + m] = v.y;
            sA[(kL + 2) * 132 + m] = v.z;
            sA[(kL + 3) * 132 + m] = v.w;
        }
#pragma unroll
        for (int p = 0; p < 2; ++p) {
            float4 v = *(const float4*)(wg + (size_t)p * 32 * DD + k0);
            int n = rowL + p * 32;
            sB[(kL + 0) * 68 + n] = v.x;
            sB[(kL + 1) * 68 + n] = v.y;
            sB[(kL + 2) * 68 + n] = v.z;
            sB[(kL + 3) * 68 + n] = v.w;
        }
        __syncthreads();
#pragma unroll
        for (int kk = 0; kk < 32; ++kk) {
            float a0, a1, a2, a3, a4, a5, a6, a7;
            LDS_V4F32(a0, a1, a2, a3, sAa + kk * 528);
            LDS_V4F32(a4, a5, a6, a7, sAa + kk * 528 + 16);
            unsigned long long b01, b23;
            LDS_V2U64(b01, b23, sBa + kk * 272);
            unsigned long long aa;
            PACK2(aa, a0); FMA2(acc[0][0], aa, b01); FMA2(acc[0][1], aa, b23);
            PACK2(aa, a1); FMA2(acc[1][0], aa, b01); FMA2(acc[1][1], aa, b23);
            PACK2(aa, a2); FMA2(acc[2][0], aa, b01); FMA2(acc[2][1], aa, b23);
            PACK2(aa, a3); FMA2(acc[3][0], aa, b01); FMA2(acc[3][1], aa, b23);
            PACK2(aa, a4); FMA2(acc[4][0], aa, b01); FMA2(acc[4][1], aa, b23);
            PACK2(aa, a5); FMA2(acc[5][0], aa, b01); FMA2(acc[5][1], aa, b23);
            PACK2(aa, a6); FMA2(acc[6][0], aa, b01); FMA2(acc[6][1], aa, b23);
            PACK2(aa, a7); FMA2(acc[7][0], aa, b01); FMA2(acc[7][1], aa, b23);
        }
        __syncthreads();
    }

    float bias[4];
#pragma unroll
    for (int c = 0; c < 4; ++c) {
        int j = bN + tx * 4 + c;
        bias[c] = bi[j] + bh[j];
    }
    float* Gd = g_G + (size_t)dir * BB * TT * G4;
#pragma unroll
    for (int i = 0; i < 8; ++i) {
        int m = bM + ty * 8 + i;
        float c0, c1, c2, c3;
        UNPACK2(c0, c1, acc[i][0]);
        UNPACK2(c2, c3, acc[i][1]);
        float4 o = make_float4(c0 + bias[0], c1 + bias[1], c2 + bias[2], c3 + bias[3]);
        *(float4*)(Gd + (size_t)m * G4 + bN + tx * 4) = o;
    }
}

// ---------------- Kernel 2: LSTM recurrence (cluster-persistent, 256 thr) ----------------
// 16 clusters of 8 CTAs: cluster = (dir, 4-batch group). CTA rank r owns hidden
// units [32r,32r+32). Thread (p,g): p=tid>>7 batch-pair, g=tid&127 gate row.
// Each thread accumulates one f32x2 (2 batches) over all 256 k — no reduction.
// h layout: [2 buf][2 pair][256 k][2 b]. Weights [64 k4][128 g][4 k] in SMEM.
#define REC_SMEM_FLOATS (32768 + 2048 + 512)
#define REC_SMEM_BYTES  (REC_SMEM_FLOATS * 4)

__global__ void __launch_bounds__(256, 1) __cluster_dims__(8, 1, 1)
lstm_rec_kernel(const float* __restrict__ whh_f, const float* __restrict__ whh_b,
                const int* __restrict__ lengths)
{
    extern __shared__ float sm[];
    float* s_w = sm;                 // [64 k4][128 g][4 k]
    float* s_h = sm + 32768;         // [2 buf][2 p][256 k][2 b]
    float* s_g = sm + 32768 + 2048;  // [128 g][4 b]

    cg::cluster_group cluster = cg::this_cluster();
    const int rank = cluster.block_rank();
    const int cidx = blockIdx.x >> 3;
    const int dir  = cidx >> 3;
    const int b0   = (cidx & 7) * 4;
    const int tid  = threadIdx.x;

    const float* whh = dir ? whh_b : whh_f;

    {   // load weight slice into [k4][g][4] layout (2 halves of k4 range)
        const int g2 = tid & 127, hf2 = tid >> 7;
        const int gt = g2 >> 5, ul = g2 & 31;
        const float* wrow = whh + (size_t)((gt << 8) + (rank << 5) + ul) * HH + hf2 * 128;
#pragma unroll 4
        for (int j = 0; j < 32; ++j) {
            float4 v = *(const float4*)(wrow + j * 4);
            *(float4*)(s_w + (size_t)(((hf2 * 32 + j) << 7) + g2) * 4) = v;
        }
    }
    for (int i = tid; i < 2048; i += 256) s_h[i] = 0.0f;
    __syncthreads();

    int L[4];
#pragma unroll
    for (int b = 0; b < 4; ++b) L[b] = lengths[b0 + b];

    float* rem[8];
#pragma unroll
    for (int r = 0; r < 8; ++r) rem[r] = cluster.map_shared_rank(s_h, r);

    cluster.sync();

    const int p  = tid >> 7;            // batch pair 0/1
    const int g  = tid & 127;           // gate row within slice
    const int gt = g >> 5, ul = g & 31;
    const int row_g = (gt << 8) + (rank << 5) + ul;
    const int bA = b0 + 2 * p, bB = bA + 1;
    const int LA = L[2 * p], LB = L[2 * p + 1];

    const int unit = tid & 127;          // activation stage
    const int half = tid >> 7;
    const int ul2 = unit >> 2, bu = unit & 3;
    const int ugl = (rank << 5) + ul2;
    const int Lu = L[bu];
    float c_state = 0.0f;

    const float* Gbase = g_G + (size_t)dir * BB * TT * G4;
    float* hbase = g_h + (size_t)dir * BB * TT * HH;

    const uint32_t wbase0  = cvta_s(s_w) + g * 16;
    const uint32_t hbase_s = cvta_s(s_h) + p * 2048;

    int cur = 0;
    for (int s = 0; s < TT; ++s) {
        // gate pre-activation prefetch for this thread's 2 batches
        int tA = dir ? (s < LA ? LA - 1 - s : s) : s;
        int tB = dir ? (s < LB ? LB - 1 - s : s) : s;
        float pA = Gbase[((size_t)bA * TT + tA) * G4 + row_g];
        float pB = Gbase[((size_t)bB * TT + tB) * G4 + row_g];

        unsigned long long a0 = 0ull, a1 = 0ull, a2 = 0ull, a3 = 0ull;
        uint32_t wa = wbase0;
        uint32_t ha = hbase_s + (cur << 12);
#pragma unroll 8
        for (int k4 = 0; k4 < 64; ++k4) {
            float w0, w1, w2, w3;
            LDS_V4F32(w0, w1, w2, w3, wa);
            unsigned long long h01a, h01b, h23a, h23b;
            LDS_V2U64(h01a, h01b, ha);
            LDS_V2U64(h23a, h23b, ha + 16);
            unsigned long long wd;
            PACK2(wd, w0); FMA2(a0, wd, h01a);
            PACK2(wd, w1); FMA2(a1, wd, h01b);
            PACK2(wd, w2); FMA2(a2, wd, h23a);
            PACK2(wd, w3); FMA2(a3, wd, h23b);
            wa += 2048;
            ha += 32;
        }
        unsigned long long s01, s23, st;
        ADD2(s01, a0, a2);
        ADD2(s23, a1, a3);
        ADD2(st, s01, s23);
        float r0, r1;
        UNPACK2(r0, r1, st);
        *(float2*)&s_g[g * 4 + 2 * p] = make_float2(r0 + pA, r1 + pB);
        __syncthreads();

        {
            float iv = s_g[(0   + ul2) * 4 + bu];
            float fv = s_g[(32  + ul2) * 4 + bu];
            float gv = s_g[(64  + ul2) * 4 + bu];
            float ov = s_g[(96  + ul2) * 4 + bu];
            float c_new = sigf(fv) * c_state + sigf(iv) * tanhf2(gv);
            float h_new = sigf(ov) * tanhf2(c_new);
            c_state = c_new;

            const int nxt = cur ^ 1;
            const int off = (nxt << 10) + ((bu >> 1) << 9) + (ugl << 1) + (bu & 1);
#pragma unroll
            for (int r = 0; r < 4; ++r) rem[half * 4 + r][off] = h_new;

            asm volatile("barrier.cluster.arrive.aligned;" ::: "memory");

            if (half == 0) {
                int tt = dir ? (s < Lu ? Lu - 1 - s : s) : s;
                hbase[((size_t)(b0 + bu) * TT + tt) * HH + ugl] = h_new;
            }
        }
        asm volatile("barrier.cluster.wait.aligned;" ::: "memory");
        cur ^= 1;
    }
}

// ---------------- Kernel 3: emissions ----------------
__global__ void __launch_bounds__(256) emis_kernel(const float* __restrict__ wtag,
                                                   const float* __restrict__ btag)
{
    __shared__ float sw[KK * 512];
    __shared__ float sb[KK];
    for (int i = threadIdx.x; i < KK * 512; i += 256) sw[i] = wtag[i];
    if (threadIdx.x < KK) sb[threadIdx.x] = btag[threadIdx.x];
    __syncthreads();

    const int warp = threadIdx.x >> 5, lane = threadIdx.x & 31;
    const size_t m = (size_t)blockIdx.x * 8 + warp;
    const float* hf = g_h + m * HH;
    const float* hb = g_h + (size_t)BB * TT * HH + m * HH;

    float acc[KK];
#pragma unroll
    for (int k = 0; k < KK; ++k) acc[k] = 0.0f;
#pragma unroll
    for (int i = 0; i < 8; ++i) {
        int idx = lane + i * 32;
        float a = hf[idx], b2 = hb[idx];
#pragma unroll
        for (int k = 0; k < KK; ++k) {
            acc[k] = fmaf(a,  sw[k * 512 + idx],       acc[k]);
            acc[k] = fmaf(b2, sw[k * 512 + 256 + idx], acc[k]);
        }
    }
#pragma unroll
    for (int k = 0; k < KK; ++k) {
        float v = acc[k];
#pragma unroll
        for (int off = 16; off; off >>= 1) v += __shfl_xor_sync(~0u, v, off);
        if (lane == 0) g_emis[m * KK + k] = v + sb[k];
    }
}

// ---------------- Kernel 4: CRF (max-free lse; spread bounded so exp is safe) ----------------
__global__ void crf_kernel(const int* __restrict__ tags, const int* __restrict__ lengths,
                           const float* __restrict__ start_trans,
                           const float* __restrict__ end_trans,
                           const float* __restrict__ trans)
{
    const int b = blockIdx.x;
    const int lane = threadIdx.x & 31;
    const int L = lengths[b];
    const float* E = g_emis + (size_t)b * TT * KK;
    const int* tg = tags + (size_t)b * TT;
    const int j  = lane & 7;
    const int i0 = (lane >> 3) * 2;
    const int i1 = i0 + 1;

    const float tc0 = trans[i0 * KK + j];
    const float tc1 = trans[i1 * KK + j];

    float sc = start_trans[j] + E[j];
    float e_nxt = E[KK + j];
    for (int t = 1; t < TT; ++t) {
        float e = e_nxt;
        if (t + 1 < TT) e_nxt = E[(t + 1) * KK + j];
        float s0 = __shfl_sync(~0u, sc, i0) + tc0;
        float s1 = __shfl_sync(~0u, sc, i1) + tc1;
        // shift by own score: cross-state spread is O(trans+emis) ~ < 30, exp-safe
        float pv = __expf(s0 - sc) + __expf(s1 - sc);
        pv += __shfl_xor_sync(~0u, pv, 8);
        pv += __shfl_xor_sync(~0u, pv, 16);
        float nxt = sc + __logf(pv) + e;
        sc = (t < L) ? nxt : sc;
    }

    float z = sc + end_trans[j];
    float mz = z;
#pragma unroll
    for (int off = 4; off; off >>= 1) mz = fmaxf(mz, __shfl_xor_sync(~0u, mz, off));
    float sz = __expf(z - mz);
#pragma unroll
    for (int off = 4; off; off >>= 1) sz += __shfl_xor_sync(~0u, sz, off);
    float logZ = mz + __logf(sz);

    float part = 0.0f;
    for (int t = 1 + lane; t < TT; t += 32)
        if (t < L) part += trans[tg[t - 1] * KK + tg[t]] + E[t * KK + tg[t]];
#pragma unroll
    for (int off = 16; off; off >>= 1) part += __shfl_xor_sync(~0u, part, off);

    if (lane == 0) {
        int t0 = tg[0];
        float num = start_trans[t0] + E[t0] + part + end_trans[tg[L - 1]];
        g_res[b] = num - logZ;
    }
}

// ---------------- Kernel 5: finalize ----------------
__global__ void finalize_kernel(float* __restrict__ out)
{
    float v = g_res[threadIdx.x];
#pragma unroll
    for (int off = 16; off; off >>= 1) v += __shfl_xor_sync(~0u, v, off);
    if (threadIdx.x == 0) out[0] = -v / (float)BB;
}

// ---------------- launch ----------------
extern "C" void kernel_launch(void* const* d_in, const int* in_sizes, int n_in,
                              void* d_out, int out_size)
{
    const float* sentences = (const float*)d_in[0];
    const int*   tags      = (const int*)  d_in[1];
    const int*   lengths   = (const int*)  d_in[2];
    const float* w_ih_f = (const float*)d_in[4];
    const float* w_hh_f = (const float*)d_in[5];
    const float* b_ih_f = (const float*)d_in[6];
    const float* b_hh_f = (const float*)d_in[7];
    const float* w_ih_b = (const float*)d_in[8];
    const float* w_hh_b = (const float*)d_in[9];
    const float* b_ih_b = (const float*)d_in[10];
    const float* b_hh_b = (const float*)d_in[11];
    const float* w_tag  = (const float*)d_in[12];
    const float* b_tag  = (const float*)d_in[13];
    const float* start_trans = (const float*)d_in[14];
    const float* end_trans   = (const float*)d_in[15];
    const float* trans       = (const float*)d_in[16];
    float* out = (float*)d_out;

    cudaFuncSetAttribute(lstm_rec_kernel,
                         cudaFuncAttributeMaxDynamicSharedMemorySize, REC_SMEM_BYTES);

    dim3 pg(512, 16, 2);
    proj_kernel<<<pg, 256>>>(sentences, w_ih_f, b_ih_f, b_hh_f, w_ih_b, b_ih_b, b_hh_b);
    lstm_rec_kernel<<<128, 256, REC_SMEM_BYTES>>>(w_hh_f, w_hh_b, lengths);
    emis_kernel<<<(BB * TT) / 8, 256>>>(w_tag, b_tag);
    crf_kernel<<<BB, 32>>>(tags, lengths, start_trans, end_trans, trans);
    finalize_kernel<<<1, 32>>>(out);
}

// round 6
// speedup vs baseline: 1.6496x; 1.6496x over previous
#include <cuda_runtime.h>
#include <cuda_bf16.h>
#include <cooperative_groups.h>
#include <cstdint>

namespace cg = cooperative_groups;

#define BB 32
#define TT 2048
#define DD 256
#define HH 256
#define G4 1024
#define KK 8

// ---------------- scratch (device globals; no runtime allocation) ----------------
__device__ float g_G[(size_t)2 * BB * TT * G4];    // gate pre-activations, both dirs
__device__ float g_h[(size_t)2 * BB * TT * HH];    // h_f / h_b (backward already un-reversed)
__device__ float g_emis[(size_t)BB * TT * KK];
__device__ float g_res[BB];

__device__ __forceinline__ uint32_t cvta_s(const void* p) {
    return (uint32_t)__cvta_generic_to_shared(p);
}

// packed f32x2 helpers (Blackwell FFMA2 path — only via PTX fma.rn.f32x2)
#define FMA2(acc, a, b) asm("fma.rn.f32x2 %0, %1, %2, %0;" : "+l"(acc) : "l"(a), "l"(b))
#define ADD2(d, a, b)   asm("add.rn.f32x2 %0, %1, %2;" : "=l"(d) : "l"(a), "l"(b))
#define PACK2(d, s)     asm("mov.b64 %0, {%1, %1};" : "=l"(d) : "f"(s))
#define PACKP(d, lo, hi) asm("mov.b64 %0, {%1, %2};" : "=l"(d) : "f"(lo), "f"(hi))
#define UNPACK2(lo, hi, v) asm("mov.b64 {%0, %1}, %2;" : "=f"(lo), "=f"(hi) : "l"(v))
#define LDS_V2U64(a, b, addr) \
    asm("ld.shared.v2.b64 {%0, %1}, [%2];" : "=l"(a), "=l"(b) : "r"(addr))
#define LDS_V4F32(w0, w1, w2, w3, addr) \
    asm("ld.shared.v4.f32 {%0, %1, %2, %3}, [%4];" \
        : "=f"(w0), "=f"(w1), "=f"(w2), "=f"(w3) : "r"(addr))

#define MBAR_INIT(addr, cnt) \
    asm volatile("mbarrier.init.shared.b64 [%0], %1;" :: "r"(addr), "r"(cnt) : "memory")
#define MBAR_ARRIVE_EXPECT(addr, bytes) \
    asm volatile("mbarrier.arrive.expect_tx.shared.b64 _, [%0], %1;" \
                 :: "r"(addr), "r"(bytes) : "memory")
#define ST_ASYNC_B32(raddr, val, rmbar) \
    asm volatile("st.async.shared::cluster.mbarrier::complete_tx::bytes.b32 [%0], %1, [%2];" \
                 :: "r"(raddr), "f"(val), "r"(rmbar) : "memory")
#define MAPA(dst, laddr, rank) \
    asm("mapa.shared::cluster.u32 %0, %1, %2;" : "=r"(dst) : "r"(laddr), "r"(rank))

__device__ __forceinline__ void mbar_wait(uint32_t mbar, uint32_t parity) {
    uint32_t done;
    asm volatile(
        "{\n\t.reg .pred p;\n\t"
        "mbarrier.try_wait.parity.acquire.cta.shared::cta.b64 p, [%1], %2;\n\t"
        "selp.b32 %0, 1, 0, p;\n\t}"
        : "=r"(done) : "r"(mbar), "r"(parity) : "memory");
    if (!done) {
        asm volatile(
            "{\n\t.reg .pred P1;\n\t"
            "WL_%=:\n\t"
            "mbarrier.try_wait.parity.acquire.cta.shared::cta.b64 P1, [%0], %1, 0x989680;\n\t"
            "@P1 bra.uni WD_%=;\n\t"
            "bra.uni WL_%=;\n\t"
            "WD_%=:\n\t}"
            :: "r"(mbar), "r"(parity) : "memory");
    }
}

__device__ __forceinline__ float sigf(float x)   { return 1.0f / (1.0f + __expf(-x)); }
__device__ __forceinline__ float tanhf2(float x) { return 2.0f / (1.0f + __expf(-2.0f * x)) - 1.0f; }

// ---------------- Kernel 1: input projection GEMM (f32x2) ----------------
__global__ void __launch_bounds__(256, 3) proj_kernel(
    const float* __restrict__ x,
    const float* __restrict__ wf, const float* __restrict__ bif, const float* __restrict__ bhf,
    const float* __restrict__ wb, const float* __restrict__ bib, const float* __restrict__ bhb)
{
    __shared__ float sA[32 * 132];
    __shared__ float sB[32 * 68];

    const int dir = blockIdx.z;
    const float* w  = dir ? wb  : wf;
    const float* bi = dir ? bib : bif;
    const float* bh = dir ? bhb : bhf;

    const int tid = threadIdx.x;
    const int bM = blockIdx.x * 128;
    const int bN = blockIdx.y * 64;
    const int ty = tid >> 4;
    const int tx = tid & 15;

    unsigned long long acc[8][2];
#pragma unroll
    for (int i = 0; i < 8; ++i) { acc[i][0] = 0ull; acc[i][1] = 0ull; }

    const int rowL = tid >> 3;
    const int kL   = (tid & 7) << 2;
    const float* xg = x + (size_t)(bM + rowL) * DD + kL;
    const float* wg = w + (size_t)(bN + rowL) * DD + kL;

    const uint32_t sAa = cvta_s(sA) + ty * 32;
    const uint32_t sBa = cvta_s(sB) + tx * 16;

    for (int kt = 0; kt < 8; ++kt) {
        const int k0 = kt * 32;
#pragma unroll
        for (int p = 0; p < 4; ++p) {
            float4 v = *(const float4*)(xg + (size_t)p * 32 * DD + k0);
            int m = rowL + p * 32;
            sA[(kL + 0) * 132 + m] = v.x;
            sA[(kL + 1) * 132 + m] = v.y;
            sA[(kL + 2) * 132 + m] = v.z;
            sA[(kL + 3) * 132 + m] = v.w;
        }
#pragma unroll
        for (int p = 0; p < 2; ++p) {
            float4 v = *(const float4*)(wg + (size_t)p * 32 * DD + k0);
            int n = rowL + p * 32;
            sB[(kL + 0) * 68 + n] = v.x;
            sB[(kL + 1) * 68 + n] = v.y;
            sB[(kL + 2) * 68 + n] = v.z;
            sB[(kL + 3) * 68 + n] = v.w;
        }
        __syncthreads();
#pragma unroll
        for (int kk = 0; kk < 32; ++kk) {
            float a0, a1, a2, a3, a4, a5, a6, a7;
            LDS_V4F32(a0, a1, a2, a3, sAa + kk * 528);
            LDS_V4F32(a4, a5, a6, a7, sAa + kk * 528 + 16);
            unsigned long long b01, b23;
            LDS_V2U64(b01, b23, sBa + kk * 272);
            unsigned long long aa;
            PACK2(aa, a0); FMA2(acc[0][0], aa, b01); FMA2(acc[0][1], aa, b23);
            PACK2(aa, a1); FMA2(acc[1][0], aa, b01); FMA2(acc[1][1], aa, b23);
            PACK2(aa, a2); FMA2(acc[2][0], aa, b01); FMA2(acc[2][1], aa, b23);
            PACK2(aa, a3); FMA2(acc[3][0], aa, b01); FMA2(acc[3][1], aa, b23);
            PACK2(aa, a4); FMA2(acc[4][0], aa, b01); FMA2(acc[4][1], aa, b23);
            PACK2(aa, a5); FMA2(acc[5][0], aa, b01); FMA2(acc[5][1], aa, b23);
            PACK2(aa, a6); FMA2(acc[6][0], aa, b01); FMA2(acc[6][1], aa, b23);
            PACK2(aa, a7); FMA2(acc[7][0], aa, b01); FMA2(acc[7][1], aa, b23);
        }
        __syncthreads();
    }

    float bias[4];
#pragma unroll
    for (int c = 0; c < 4; ++c) {
        int j = bN + tx * 4 + c;
        bias[c] = bi[j] + bh[j];
    }
    float* Gd = g_G + (size_t)dir * BB * TT * G4;
#pragma unroll
    for (int i = 0; i < 8; ++i) {
        int m = bM + ty * 8 + i;
        float c0, c1, c2, c3;
        UNPACK2(c0, c1, acc[i][0]);
        UNPACK2(c2, c3, acc[i][1]);
        float4 o = make_float4(c0 + bias[0], c1 + bias[1], c2 + bias[2], c3 + bias[3]);
        *(float4*)(Gd + (size_t)m * G4 + bN + tx * 4) = o;
    }
}

// ---------------- noop (shifts ncu capture index so rec gets profiled) ----------------
__global__ void noop_kernel() {}

// ---------------- Kernel 2: LSTM recurrence (register weights + st.async) ----------------
// 16 clusters of 8 CTAs: cluster = (dir, 4-batch group). CTA rank r owns hidden
// units [32r,32r+32) → gate rows gt*256 + 32r + ul, g = gt*32+ul ∈ [0,128).
// 256 threads: kh = tid>>7 (k half), g = tid&127. Each thread holds w_hh[row_g]
// [kh*128 .. kh*128+128) in 128 REGISTERS. h[2 buf][256 k][4 b] in smem (broadcast
// reads). Partials in s_part[2][128][4]. kh=1 threads (tid>=128) run activations
// and push h_{s+1} to all 8 ranks via st.async with tx-counted ping-pong mbarriers.
#define REC_SMEM_FLOATS (2048 + 1024)
#define REC_SMEM_BYTES  (REC_SMEM_FLOATS * 4)
#define RECV_BYTES      4096u   // 8 ranks * 128 values * 4 B per step

__global__ void __launch_bounds__(256, 1) __cluster_dims__(8, 1, 1)
lstm_rec_kernel(const float* __restrict__ whh_f, const float* __restrict__ whh_b,
                const int* __restrict__ lengths)
{
    extern __shared__ float sm[];
    float* s_h    = sm;            // [2 buf][256 k][4 b]
    float* s_part = sm + 2048;     // [2 kh][128 g][4 b]
    __shared__ __align__(8) unsigned long long s_bar[2];

    cg::cluster_group cluster = cg::this_cluster();
    const int rank = cluster.block_rank();
    const int cidx = blockIdx.x >> 3;
    const int dir  = cidx >> 3;
    const int b0   = (cidx & 7) * 4;
    const int tid  = threadIdx.x;
    const int kh   = tid >> 7;
    const int g    = tid & 127;

    const float* whh = dir ? whh_b : whh_f;

    const int gt = g >> 5, ul = g & 31;
    const int row_g = (gt << 8) + (rank << 5) + ul;

    // weight slice into registers: w[row_g][kh*128 + 0..127]
    float4 wreg[32];
    {
        const float4* wrow = (const float4*)(whh + (size_t)row_g * HH + kh * 128);
#pragma unroll
        for (int j = 0; j < 32; ++j) wreg[j] = wrow[j];
    }

    for (int i = tid; i < 2048; i += 256) s_h[i] = 0.0f;

    const uint32_t bar0 = cvta_s(&s_bar[0]);
    const uint32_t bar1 = cvta_s(&s_bar[1]);
    if (tid == 0) {
        MBAR_INIT(bar0, 1);
        MBAR_INIT(bar1, 1);
    }
    __syncthreads();
    cluster.sync();          // all barriers initialized cluster-wide
    if (tid == 0) {          // pre-post expects: bar1 <- h1 (iter0), bar0 <- h2 (iter1)
        MBAR_ARRIVE_EXPECT(bar0, RECV_BYTES);
        MBAR_ARRIVE_EXPECT(bar1, RECV_BYTES);
    }

    int L[4];
#pragma unroll
    for (int b = 0; b < 4; ++b) L[b] = lengths[b0 + b];

    // remote addresses (shared::cluster) for h buffers and barriers
    const uint32_t sh_u32 = cvta_s(s_h);
    uint32_t rem_h[8], rem_b0[8], rem_b1[8];
#pragma unroll
    for (int r = 0; r < 8; ++r) {
        MAPA(rem_h[r], sh_u32, r);
        MAPA(rem_b0[r], bar0, r);
        MAPA(rem_b1[r], bar1, r);
    }

    // activation-thread mapping (kh == 1)
    const int t2  = g;
    const int ul2 = t2 >> 2, bu = t2 & 3;
    const int ugl = (rank << 5) + ul2;
    const int Lu  = L[bu];
    float c_state = 0.0f;

    const int LA = L[0], LB = L[1], LC = L[2], LD = L[3];

    const float* Gbase = g_G + (size_t)dir * BB * TT * G4;
    float* hbase = g_h + (size_t)dir * BB * TT * HH;

    const uint32_t part_a = cvta_s(s_part) + (kh * 128 + g) * 16;
    const uint32_t act_a  = cvta_s(s_part) + t2 * 4;   // + gate*512, + half*2048

    uint32_t ph0 = 0, ph1 = 0;
    int cur = 0;
    for (int s = 0; s < TT; ++s) {
        float p0, p1, p2, p3;
        if (kh == 0) {   // G prefetch, issued before the barrier wait
            int tA = dir ? (s < LA ? LA - 1 - s : s) : s;
            int tB = dir ? (s < LB ? LB - 1 - s : s) : s;
            int tC = dir ? (s < LC ? LC - 1 - s : s) : s;
            int tD = dir ? (s < LD ? LD - 1 - s : s) : s;
            p0 = Gbase[((size_t)(b0 + 0) * TT + tA) * G4 + row_g];
            p1 = Gbase[((size_t)(b0 + 1) * TT + tB) * G4 + row_g];
            p2 = Gbase[((size_t)(b0 + 2) * TT + tC) * G4 + row_g];
            p3 = Gbase[((size_t)(b0 + 3) * TT + tD) * G4 + row_g];
        }

        if (s > 0) {
            if (s & 1) { mbar_wait(bar1, ph1); ph1 ^= 1; if (tid == 0) MBAR_ARRIVE_EXPECT(bar1, RECV_BYTES); }
            else       { mbar_wait(bar0, ph0); ph0 ^= 1; if (tid == 0) MBAR_ARRIVE_EXPECT(bar0, RECV_BYTES); }
        }

        // matvec: acc over this thread's 128-k range, weights in registers
        unsigned long long a01e = 0ull, a23e = 0ull, a01o = 0ull, a23o = 0ull;
        uint32_t ha = sh_u32 + (cur << 12) + kh * 2048;
#pragma unroll
        for (int j = 0; j < 32; ++j) {
            float4 wv = wreg[j];
            unsigned long long h01, h23, wd;
            LDS_V2U64(h01, h23, ha);
            PACK2(wd, wv.x); FMA2(a01e, wd, h01); FMA2(a23e, wd, h23);
            LDS_V2U64(h01, h23, ha + 16);
            PACK2(wd, wv.y); FMA2(a01o, wd, h01); FMA2(a23o, wd, h23);
            LDS_V2U64(h01, h23, ha + 32);
            PACK2(wd, wv.z); FMA2(a01e, wd, h01); FMA2(a23e, wd, h23);
            LDS_V2U64(h01, h23, ha + 48);
            PACK2(wd, wv.w); FMA2(a01o, wd, h01); FMA2(a23o, wd, h23);
            ha += 64;
        }
        unsigned long long a01, a23;
        ADD2(a01, a01e, a01o);
        ADD2(a23, a23e, a23o);
        if (kh == 0) {   // fold in gate pre-activations
            unsigned long long gp;
            PACKP(gp, p0, p1); ADD2(a01, a01, gp);
            PACKP(gp, p2, p3); ADD2(a23, a23, gp);
        }
        asm volatile("st.shared.v2.b64 [%0], {%1, %2};" :: "r"(part_a), "l"(a01), "l"(a23) : "memory");
        __syncthreads();

        if (kh == 1) {   // activation + remote scatter
            float iv = s_part[(0 * 32 + ul2) * 4 + bu] + s_part[512 + (0 * 32 + ul2) * 4 + bu];
            float fv = s_part[(1 * 32 + ul2) * 4 + bu] + s_part[512 + (1 * 32 + ul2) * 4 + bu];
            float gv = s_part[(2 * 32 + ul2) * 4 + bu] + s_part[512 + (2 * 32 + ul2) * 4 + bu];
            float ov = s_part[(3 * 32 + ul2) * 4 + bu] + s_part[512 + (3 * 32 + ul2) * 4 + bu];
            float c_new = sigf(fv) * c_state + sigf(iv) * tanhf2(gv);
            float h_new = sigf(ov) * tanhf2(c_new);
            c_state = c_new;

            const int nxt = cur ^ 1;
            const uint32_t off = ((nxt << 10) + (ugl << 2) + bu) * 4;
            const int sb = (s + 1) & 1;
#pragma unroll
            for (int r = 0; r < 8; ++r)
                ST_ASYNC_B32(rem_h[r] + off, h_new, sb ? rem_b1[r] : rem_b0[r]);

            int tt = dir ? (s < Lu ? Lu - 1 - s : s) : s;
            hbase[((size_t)(b0 + bu) * TT + tt) * HH + ugl] = h_new;
        }
        cur ^= 1;
    }
    cluster.sync();   // protect in-flight final st.asyncs before exit
}

// ---------------- Kernel 3: emissions ----------------
__global__ void __launch_bounds__(256) emis_kernel(const float* __restrict__ wtag,
                                                   const float* __restrict__ btag)
{
    __shared__ float sw[KK * 512];
    __shared__ float sb[KK];
    for (int i = threadIdx.x; i < KK * 512; i += 256) sw[i] = wtag[i];
    if (threadIdx.x < KK) sb[threadIdx.x] = btag[threadIdx.x];
    __syncthreads();

    const int warp = threadIdx.x >> 5, lane = threadIdx.x & 31;
    const size_t m = (size_t)blockIdx.x * 8 + warp;
    const float* hf = g_h + m * HH;
    const float* hb = g_h + (size_t)BB * TT * HH + m * HH;

    float acc[KK];
#pragma unroll
    for (int k = 0; k < KK; ++k) acc[k] = 0.0f;
#pragma unroll
    for (int i = 0; i < 8; ++i) {
        int idx = lane + i * 32;
        float a = hf[idx], b2 = hb[idx];
#pragma unroll
        for (int k = 0; k < KK; ++k) {
            acc[k] = fmaf(a,  sw[k * 512 + idx],       acc[k]);
            acc[k] = fmaf(b2, sw[k * 512 + 256 + idx], acc[k]);
        }
    }
#pragma unroll
    for (int k = 0; k < KK; ++k) {
        float v = acc[k];
#pragma unroll
        for (int off = 16; off; off >>= 1) v += __shfl_xor_sync(~0u, v, off);
        if (lane == 0) g_emis[m * KK + k] = v + sb[k];
    }
}

// ---------------- Kernel 4: CRF (4-deep E prefetch; max-free lse) ----------------
__global__ void crf_kernel(const int* __restrict__ tags, const int* __restrict__ lengths,
                           const float* __restrict__ start_trans,
                           const float* __restrict__ end_trans,
                           const float* __restrict__ trans)
{
    const int b = blockIdx.x;
    const int lane = threadIdx.x & 31;
    const int L = lengths[b];
    const float* E = g_emis + (size_t)b * TT * KK;
    const int* tg = tags + (size_t)b * TT;
    const int j  = lane & 7;
    const int i0 = (lane >> 3) * 2;
    const int i1 = i0 + 1;

    const float tc0 = trans[i0 * KK + j];
    const float tc1 = trans[i1 * KK + j];

    float sc = start_trans[j] + E[j];
    float e1 = E[1 * KK + j], e2 = E[2 * KK + j], e3 = E[3 * KK + j], e4 = E[4 * KK + j];
#pragma unroll 4
    for (int t = 1; t < TT; ++t) {
        float e = e1; e1 = e2; e2 = e3; e3 = e4;
        if (t + 4 < TT) e4 = E[(t + 4) * KK + j];
        float s0 = __shfl_sync(~0u, sc, i0) + tc0;
        float s1 = __shfl_sync(~0u, sc, i1) + tc1;
        float pv = __expf(s0 - sc) + __expf(s1 - sc);
        pv += __shfl_xor_sync(~0u, pv, 8);
        pv += __shfl_xor_sync(~0u, pv, 16);
        float nxt = sc + __logf(pv) + e;
        sc = (t < L) ? nxt : sc;
    }

    float z = sc + end_trans[j];
    float mz = z;
#pragma unroll
    for (int off = 4; off; off >>= 1) mz = fmaxf(mz, __shfl_xor_sync(~0u, mz, off));
    float sz = __expf(z - mz);
#pragma unroll
    for (int off = 4; off; off >>= 1) sz += __shfl_xor_sync(~0u, sz, off);
    float logZ = mz + __logf(sz);

    float part = 0.0f;
    for (int t = 1 + lane; t < TT; t += 32)
        if (t < L) part += trans[tg[t - 1] * KK + tg[t]] + E[t * KK + tg[t]];
#pragma unroll
    for (int off = 16; off; off >>= 1) part += __shfl_xor_sync(~0u, part, off);

    if (lane == 0) {
        int t0 = tg[0];
        float num = start_trans[t0] + E[t0] + part + end_trans[tg[L - 1]];
        g_res[b] = num - logZ;
    }
}

// ---------------- Kernel 5: finalize ----------------
__global__ void finalize_kernel(float* __restrict__ out)
{
    float v = g_res[threadIdx.x];
#pragma unroll
    for (int off = 16; off; off >>= 1) v += __shfl_xor_sync(~0u, v, off);
    if (threadIdx.x == 0) out[0] = -v / (float)BB;
}

// ---------------- launch ----------------
extern "C" void kernel_launch(void* const* d_in, const int* in_sizes, int n_in,
                              void* d_out, int out_size)
{
    const float* sentences = (const float*)d_in[0];
    const int*   tags      = (const int*)  d_in[1];
    const int*   lengths   = (const int*)  d_in[2];
    const float* w_ih_f = (const float*)d_in[4];
    const float* w_hh_f = (const float*)d_in[5];
    const float* b_ih_f = (const float*)d_in[6];
    const float* b_hh_f = (const float*)d_in[7];
    const float* w_ih_b = (const float*)d_in[8];
    const float* w_hh_b = (const float*)d_in[9];
    const float* b_ih_b = (const float*)d_in[10];
    const float* b_hh_b = (const float*)d_in[11];
    const float* w_tag  = (const float*)d_in[12];
    const float* b_tag  = (const float*)d_in[13];
    const float* start_trans = (const float*)d_in[14];
    const float* end_trans   = (const float*)d_in[15];
    const float* trans       = (const float*)d_in[16];
    float* out = (float*)d_out;

    dim3 pg(512, 16, 2);
    proj_kernel<<<pg, 256>>>(sentences, w_ih_f, b_ih_f, b_hh_f, w_ih_b, b_ih_b, b_hh_b);
    noop_kernel<<<1, 32>>>();
    noop_kernel<<<1, 32>>>();
    lstm_rec_kernel<<<128, 256, REC_SMEM_BYTES>>>(w_hh_f, w_hh_b, lengths);
    emis_kernel<<<(BB * TT) / 8, 256>>>(w_tag, b_tag);
    crf_kernel<<<BB, 32>>>(tags, lengths, start_trans, end_trans, trans);
    finalize_kernel<<<1, 32>>>(out);
}